// round 2
// baseline (speedup 1.0000x reference)
#include <cuda_runtime.h>
#include <math.h>

#define B_    32
#define S_    2048
#define H_    256
#define V_    50000
#define OOV_  12
#define VEXT_ 50012
#define M_    (B_*S_)
#define KD_   512
#define XD_   768

#define OFF_STATE 1600384
#define OFF_W     1608576

typedef unsigned long long ull;

__device__ __align__(16) float g_xT[XD_*B_];
__device__ __align__(16) float g_hT[H_*B_];
__device__ __align__(16) float g_gx[768*B_];
__device__ __align__(16) float g_gh[768*B_];
__device__ __align__(16) float g_state[B_*H_];
__device__ __align__(16) float g_WcT[KD_*H_];
__device__ __align__(16) float g_score_g[B_*V_];
__device__ __align__(16) float g_score_c[M_];
__device__ __align__(16) float g_prob_c[M_];
__device__            int   g_counts[VEXT_];
__device__            int   g_rs[B_];
__device__ __align__(16) float g_rowsums[B_*VEXT_];

__device__ __forceinline__ ull ffma2(ull a, ull b, ull c) {
    ull d; asm("fma.rn.f32x2 %0, %1, %2, %3;" : "=l"(d) : "l"(a), "l"(b), "l"(c)); return d;
}
__device__ __forceinline__ ull pk2(float lo, float hi) {
    ull r; asm("mov.b64 %0, {%1, %2};" : "=l"(r) : "f"(lo), "f"(hi)); return r;
}
__device__ __forceinline__ void upk2(ull v, float& lo, float& hi) {
    asm("mov.b64 {%0, %1}, %2;" : "=f"(lo), "=f"(hi) : "l"(v));
}
__device__ __forceinline__ float sigm(float x) { return 1.f / (1.f + expf(-x)); }

// ---- K0: zero scratch, zero weighted-out region, transpose Wc, gather x/h transposed ----
__global__ void k_prep(const int* __restrict__ input_idx, const float* __restrict__ embed,
                       const float* __restrict__ weighted, const float* __restrict__ prev_state,
                       const float* __restrict__ Wc_w, float* __restrict__ out)
{
    const int N0 = VEXT_;
    const int N1 = B_*VEXT_;
    const int N2 = KD_*H_;
    const int N3 = XD_*B_;
    const int N4 = H_*B_;
    const int N5 = B_*512;
    const int total = N0+N1+N2+N3+N4+N5+B_;
    for (int gid = blockIdx.x*blockDim.x + threadIdx.x; gid < total; gid += gridDim.x*blockDim.x) {
        int i = gid;
        if (i < N0) { g_counts[i] = 0; continue; }
        i -= N0;
        if (i < N1) { g_rowsums[i] = 0.f; continue; }
        i -= N1;
        if (i < N2) { int k = i >> 8; int n = i & 255; g_WcT[i] = Wc_w[n*KD_ + k]; continue; }
        i -= N2;
        if (i < N3) {
            int k = i >> 5; int b = i & 31;
            g_xT[i] = (k < 256) ? embed[(size_t)input_idx[b]*256 + k] : weighted[b*512 + (k-256)];
            continue;
        }
        i -= N3;
        if (i < N4) { int k = i >> 5; int b = i & 31; g_hT[i] = prev_state[b*H_ + k]; continue; }
        i -= N4;
        if (i < N5) { out[OFF_W + i] = 0.f; continue; }
        i -= N5;
        g_rs[i] = 0;
    }
}

// ---- K0b: global duplicate histogram + per-row match count ----
__global__ void k_counts(const int* __restrict__ eidx, const int* __restrict__ input_idx) {
    int gid = blockIdx.x*blockDim.x + threadIdx.x;
    if (gid < M_) {
        int idx = eidx[gid];
        atomicAdd(&g_counts[idx], 1);
        int b = gid >> 11;
        if (idx == input_idx[b]) atomicAdd(&g_rs[b], 1);
    }
}

// ---- K1: GRU gemms, warp lanes = batch ----
__global__ void k_gru_gemm(const float* __restrict__ w_ih, const float* __restrict__ w_hh) {
    const int tid = threadIdx.x;
    const int b = tid & 31;
    const int j = blockIdx.x*8 + (tid >> 5);
    if (blockIdx.y == 0) {
        const float4* wr = (const float4*)(w_ih + (size_t)j*XD_);
        float acc = 0.f;
        #pragma unroll 8
        for (int k4 = 0; k4 < XD_/4; ++k4) {
            float4 wv = wr[k4];
            int k = k4*4;
            acc += wv.x*g_xT[(k+0)*32+b] + wv.y*g_xT[(k+1)*32+b]
                 + wv.z*g_xT[(k+2)*32+b] + wv.w*g_xT[(k+3)*32+b];
        }
        g_gx[j*32+b] = acc;
    } else {
        const float4* wr = (const float4*)(w_hh + (size_t)j*H_);
        float acc = 0.f;
        #pragma unroll 8
        for (int k4 = 0; k4 < H_/4; ++k4) {
            float4 wv = wr[k4];
            int k = k4*4;
            acc += wv.x*g_hT[(k+0)*32+b] + wv.y*g_hT[(k+1)*32+b]
                 + wv.z*g_hT[(k+2)*32+b] + wv.w*g_hT[(k+3)*32+b];
        }
        g_gh[j*32+b] = acc;
    }
}

// ---- K2: gates -> state ----
__global__ void k_gates(const float* __restrict__ b_ih, const float* __restrict__ b_hh,
                        const float* __restrict__ prev_state, float* __restrict__ out)
{
    const int b = blockIdx.x, h = threadIdx.x;
    float xr = g_gx[h*32+b]        + b_ih[h];
    float xz = g_gx[(256+h)*32+b]  + b_ih[256+h];
    float xn = g_gx[(512+h)*32+b]  + b_ih[512+h];
    float hr = g_gh[h*32+b]        + b_hh[h];
    float hz = g_gh[(256+h)*32+b]  + b_hh[256+h];
    float hn = g_gh[(512+h)*32+b]  + b_hh[512+h];
    float r = sigm(xr + hr);
    float z = sigm(xz + hz);
    float n = tanhf(xn + r*hn);
    float st = (1.f - z)*n + z*prev_state[b*H_+h];
    g_state[b*H_+h] = st;
    out[OFF_STATE + b*H_ + h] = st;
}

// ---- K3: score_g = state @ Wo^T + Wo_b. warp: lane=b, 4 v per warp ----
__global__ __launch_bounds__(256) void k_score_g(const float* __restrict__ Wo_w,
                                                 const float* __restrict__ Wo_b)
{
    __shared__ float st_s[H_*32];
    const int tid = threadIdx.x;
    for (int i = tid; i < H_*32; i += 256) {
        int k = i >> 5, b = i & 31;
        st_s[i] = g_state[b*H_ + k];
    }
    __syncthreads();
    const int lane = tid & 31;
    const int v0 = blockIdx.x*32 + (tid >> 5)*4;
    if (v0 >= V_) return;
    const float4* w0 = (const float4*)(Wo_w + (size_t)(v0+0)*H_);
    const float4* w1 = (const float4*)(Wo_w + (size_t)(v0+1)*H_);
    const float4* w2 = (const float4*)(Wo_w + (size_t)(v0+2)*H_);
    const float4* w3 = (const float4*)(Wo_w + (size_t)(v0+3)*H_);
    float a0=0.f, a1=0.f, a2=0.f, a3=0.f;
    #pragma unroll 4
    for (int k4 = 0; k4 < H_/4; ++k4) {
        float s0 = st_s[(k4*4+0)*32 + lane];
        float s1 = st_s[(k4*4+1)*32 + lane];
        float s2 = st_s[(k4*4+2)*32 + lane];
        float s3 = st_s[(k4*4+3)*32 + lane];
        float4 q;
        q = w0[k4]; a0 += q.x*s0 + q.y*s1 + q.z*s2 + q.w*s3;
        q = w1[k4]; a1 += q.x*s0 + q.y*s1 + q.z*s2 + q.w*s3;
        q = w2[k4]; a2 += q.x*s0 + q.y*s1 + q.z*s2 + q.w*s3;
        q = w3[k4]; a3 += q.x*s0 + q.y*s1 + q.z*s2 + q.w*s3;
    }
    float4 r;
    r.x = a0 + Wo_b[v0+0];
    r.y = a1 + Wo_b[v0+1];
    r.z = a2 + Wo_b[v0+2];
    r.w = a3 + Wo_b[v0+3];
    *(float4*)(g_score_g + (size_t)lane*V_ + v0) = r;
}

// ---- K4: fused sc = tanh(enc@Wc^T + b); score_c = tanh(sc . state) + mask ----
// tile 128(m) x 256(n), K=512 in 64 steps of BK=8. 512 threads, 8x8 micro, f32x2 acc.
__global__ __launch_bounds__(512, 1) void k_score_c(const float* __restrict__ enc,
                                                    const int* __restrict__ eidx,
                                                    const float* __restrict__ wcb)
{
    __shared__ __align__(16) float As[2][8][132];
    __shared__ __align__(16) float Bs[2][8][256];
    __shared__ float st_s[256];
    __shared__ float bi_s[256];

    const int tid = threadIdx.x;
    const int m0  = blockIdx.x * 128;
    const int b   = m0 >> 11;
    if (tid < 256) { st_s[tid] = g_state[b*H_ + tid]; bi_s[tid] = wcb[tid]; }

    const int tn = tid & 31;
    const int tm = tid >> 5;

    const int arow = tid >> 1;
    const int akq  = tid & 1;
    const int bk   = tid >> 6;
    const int bnq  = tid & 63;

    const float* aG = enc + (size_t)(m0 + arow)*KD_ + akq*4;
    const float* bG = g_WcT + (size_t)bk*256 + bnq*4;

    ull acc[8][4];
    #pragma unroll
    for (int i = 0; i < 8; ++i)
        #pragma unroll
        for (int j = 0; j < 4; ++j) acc[i][j] = 0ULL;

    float4 ra, rb;
    if (tid < 256) ra = *(const float4*)(aG);
    rb = *(const float4*)(bG);
    if (tid < 256) {
        As[0][akq*4+0][arow] = ra.x; As[0][akq*4+1][arow] = ra.y;
        As[0][akq*4+2][arow] = ra.z; As[0][akq*4+3][arow] = ra.w;
    }
    *(float4*)&Bs[0][bk][bnq*4] = rb;
    __syncthreads();

    #pragma unroll 1
    for (int kt = 0; kt < 64; ++kt) {
        const int cur = kt & 1;
        if (kt < 63) {
            if (tid < 256) ra = *(const float4*)(aG + (kt+1)*8);
            rb = *(const float4*)(bG + (size_t)(kt+1)*8*256);
        }
        #pragma unroll
        for (int k = 0; k < 8; ++k) {
            float4 a0 = *(const float4*)&As[cur][k][tm*8];
            float4 a1 = *(const float4*)&As[cur][k][tm*8 + 4];
            ulonglong2 bv0 = *(const ulonglong2*)&Bs[cur][k][tn*4];
            ulonglong2 bv1 = *(const ulonglong2*)&Bs[cur][k][128 + tn*4];
            float av[8] = {a0.x,a0.y,a0.z,a0.w,a1.x,a1.y,a1.z,a1.w};
            ull bp[4] = {bv0.x, bv0.y, bv1.x, bv1.y};
            #pragma unroll
            for (int i = 0; i < 8; ++i) {
                ull a2 = pk2(av[i], av[i]);
                #pragma unroll
                for (int j = 0; j < 4; ++j) acc[i][j] = ffma2(a2, bp[j], acc[i][j]);
            }
        }
        __syncthreads();
        if (kt < 63) {
            const int nxt = 1 - cur;
            if (tid < 256) {
                As[nxt][akq*4+0][arow] = ra.x; As[nxt][akq*4+1][arow] = ra.y;
                As[nxt][akq*4+2][arow] = ra.z; As[nxt][akq*4+3][arow] = ra.w;
            }
            *(float4*)&Bs[nxt][bk][bnq*4] = rb;
            __syncthreads();
        }
    }

    // epilogue: tanh -> dot with state -> warp reduce -> outer tanh + mask
    #pragma unroll
    for (int i = 0; i < 8; ++i) {
        float p = 0.f;
        #pragma unroll
        for (int j = 0; j < 4; ++j) {
            float c0, c1; upk2(acc[i][j], c0, c1);
            int n0 = (j < 2) ? (tn*4 + 2*j) : (128 + tn*4 + 2*(j-2));
            p += tanhf(c0 + bi_s[n0])   * st_s[n0];
            p += tanhf(c1 + bi_s[n0+1]) * st_s[n0+1];
        }
        #pragma unroll
        for (int o = 16; o; o >>= 1) p += __shfl_down_sync(0xffffffffu, p, o);
        if (tn == 0) {
            int m = m0 + tm*8 + i;
            float v = tanhf(p);
            if (eidx[m] == 0) v -= 1000.f;
            g_score_c[m] = v;
        }
    }
}

// ---- K5: joint softmax over [score_g | score_c] ----
__global__ __launch_bounds__(1024) void k_softmax(float* __restrict__ out) {
    __shared__ float red[32];
    const int b = blockIdx.x, tid = threadIdx.x;
    const float* sg = g_score_g + (size_t)b*V_;
    const float* sc = g_score_c + b*S_;

    float mx = -1e30f;
    for (int i = tid; i < V_; i += 1024) mx = fmaxf(mx, sg[i]);
    for (int i = tid; i < S_; i += 1024) mx = fmaxf(mx, sc[i]);
    #pragma unroll
    for (int o = 16; o; o >>= 1) mx = fmaxf(mx, __shfl_xor_sync(0xffffffffu, mx, o));
    if ((tid & 31) == 0) red[tid >> 5] = mx;
    __syncthreads();
    if (tid < 32) {
        float v = red[tid];
        #pragma unroll
        for (int o = 16; o; o >>= 1) v = fmaxf(v, __shfl_xor_sync(0xffffffffu, v, o));
        red[tid] = v;
    }
    __syncthreads();
    mx = red[0];
    __syncthreads();

    float sum = 0.f;
    for (int i = tid; i < V_; i += 1024) sum += expf(sg[i] - mx);
    for (int i = tid; i < S_; i += 1024) sum += expf(sc[i] - mx);
    #pragma unroll
    for (int o = 16; o; o >>= 1) sum += __shfl_xor_sync(0xffffffffu, sum, o);
    if ((tid & 31) == 0) red[tid >> 5] = sum;
    __syncthreads();
    if (tid < 32) {
        float v = red[tid];
        #pragma unroll
        for (int o = 16; o; o >>= 1) v += __shfl_xor_sync(0xffffffffu, v, o);
        red[tid] = v;
    }
    __syncthreads();
    const float inv = 1.f / red[0];

    float* og = out + (size_t)b*VEXT_;
    for (int i = tid; i < V_; i += 1024) og[i] = expf(sg[i] - mx) * inv;
    for (int i = tid; i < S_; i += 1024) g_prob_c[b*S_ + i] = expf(sc[i] - mx) * inv;
    if (tid < OOV_) og[V_ + tid] = 1e-4f;
}

// ---- K6: per-row scatter sums of prob_c ----
__global__ void k_rowsums(const int* __restrict__ eidx) {
    int gid = blockIdx.x*blockDim.x + threadIdx.x;
    if (gid < M_) {
        int b = gid >> 11;
        atomicAdd(&g_rowsums[(size_t)b*VEXT_ + eidx[gid]], g_prob_c[gid]);
    }
}

// ---- K7: attn scatter into out, sparse weighted_out ----
__global__ void k_final(const int* __restrict__ eidx, const int* __restrict__ input_idx,
                        const float* __restrict__ enc, float* __restrict__ out)
{
    int gid = blockIdx.x*blockDim.x + threadIdx.x;
    if (gid >= M_) return;
    int b = gid >> 11;
    int idx = eidx[gid];
    float pc = g_prob_c[gid];
    float attn = pc;
    if (g_counts[idx] > 1) attn = pc * g_rowsums[(size_t)b*VEXT_ + idx];
    atomicAdd(&out[(size_t)b*VEXT_ + idx], attn);

    if (idx == input_idx[b]) {
        int rs = g_rs[b];
        float f = (rs > 1) ? (1.f / (float)rs) : 1.f;
        float a2 = pc * f;
        const float* er = enc + (size_t)gid*KD_;
        for (int d = 0; d < KD_; ++d)
            atomicAdd(&out[OFF_W + b*512 + d], a2 * er[d]);
    }
}

extern "C" void kernel_launch(void* const* d_in, const int* in_sizes, int n_in,
                              void* d_out, int out_size)
{
    const int*   input_idx = (const int*)  d_in[0];
    const float* encoded   = (const float*)d_in[1];
    const int*   eidx      = (const int*)  d_in[2];
    const float* prev_st   = (const float*)d_in[3];
    const float* weighted  = (const float*)d_in[4];
    const float* embed     = (const float*)d_in[6];
    const float* w_ih      = (const float*)d_in[7];
    const float* w_hh      = (const float*)d_in[8];
    const float* b_ih      = (const float*)d_in[9];
    const float* b_hh      = (const float*)d_in[10];
    const float* Wo_w      = (const float*)d_in[11];
    const float* Wo_b      = (const float*)d_in[12];
    const float* Wc_w      = (const float*)d_in[13];
    const float* Wc_b      = (const float*)d_in[14];
    float* out = (float*)d_out;

    k_prep<<<4096, 256>>>(input_idx, embed, weighted, prev_st, Wc_w, out);
    k_counts<<<M_/256, 256>>>(eidx, input_idx);
    k_gru_gemm<<<dim3(96, 2), 256>>>(w_ih, w_hh);
    k_gates<<<B_, H_>>>(b_ih, b_hh, prev_st, out);
    k_score_g<<<(V_ + 31)/32, 256>>>(Wo_w, Wo_b);
    k_score_c<<<M_/128, 512>>>(encoded, eidx, Wc_b);
    k_softmax<<<B_, 1024>>>(out);
    k_rowsums<<<M_/256, 256>>>(eidx);
    k_final<<<M_/256, 256>>>(eidx, input_idx, encoded, out);
}

// round 4
// speedup vs baseline: 1.5750x; 1.5750x over previous
#include <cuda_runtime.h>
#include <cuda_bf16.h>
#include <math.h>

#define B_    32
#define S_    2048
#define H_    256
#define V_    50000
#define OOV_  12
#define VEXT_ 50012
#define M_    (B_*S_)
#define KD_   512
#define XD_   768
#define TOT_  (V_ + S_)
#define NCH_  13

#define OFF_STATE 1600384
#define OFF_W     1608576

// ---------------- scratch ----------------
__device__ __align__(16) float g_xT[XD_*B_];
__device__ __align__(16) float g_hT[H_*B_];
__device__ __align__(16) float g_gx[768*B_];
__device__ __align__(16) float g_gh[768*B_];
__device__ __align__(16) float g_state[B_*H_];
__device__ __align__(16) float g_score_g[B_*V_];
__device__ __align__(16) float g_score_c[M_];
__device__ __align__(16) float g_prob_c[M_];
__device__            int   g_counts[VEXT_];
__device__            int   g_rs[B_];
__device__ __align__(16) float g_rowsums[B_*VEXT_];
// Wc split into bf16 hi/lo, [n][k] row-major (n<256, k<512)
__device__ __align__(16) __nv_bfloat16 g_WcH[H_*KD_];
__device__ __align__(16) __nv_bfloat16 g_WcL[H_*KD_];
// softmax partials
__device__ float g_pm[B_*NCH_];
__device__ float g_ps[B_*NCH_];
__device__ float g_scale[B_*NCH_];

__device__ __forceinline__ float sigm(float x) { return 1.f / (1.f + expf(-x)); }

__device__ __forceinline__ void hmma16816(float* c, const unsigned* a, const unsigned* b) {
    asm volatile(
        "mma.sync.aligned.m16n8k16.row.col.f32.bf16.bf16.f32 "
        "{%0,%1,%2,%3}, {%4,%5,%6,%7}, {%8,%9}, {%0,%1,%2,%3};"
        : "+f"(c[0]), "+f"(c[1]), "+f"(c[2]), "+f"(c[3])
        : "r"(a[0]), "r"(a[1]), "r"(a[2]), "r"(a[3]), "r"(b[0]), "r"(b[1]));
}

// ---- K0: zero scratch + Wc bf16 hi/lo split + gathers ----
__global__ void k_prep(const int* __restrict__ input_idx, const float* __restrict__ embed,
                       const float* __restrict__ weighted, const float* __restrict__ prev_state,
                       const float* __restrict__ Wc_w, float* __restrict__ out)
{
    const int N0 = VEXT_;
    const int N1 = B_*VEXT_;
    const int N2 = H_*KD_;
    const int N3 = XD_*B_;
    const int N4 = H_*B_;
    const int N5 = B_*512;
    const int total = N0+N1+N2+N3+N4+N5+B_;
    for (int gid = blockIdx.x*blockDim.x + threadIdx.x; gid < total; gid += gridDim.x*blockDim.x) {
        int i = gid;
        if (i < N0) { g_counts[i] = 0; continue; }
        i -= N0;
        if (i < N1) { g_rowsums[i] = 0.f; continue; }
        i -= N1;
        if (i < N2) {
            float x = Wc_w[i];
            __nv_bfloat16 h = __float2bfloat16(x);
            g_WcH[i] = h;
            g_WcL[i] = __float2bfloat16(x - __bfloat162float(h));
            continue;
        }
        i -= N2;
        if (i < N3) {
            int k = i >> 5; int b = i & 31;
            g_xT[i] = (k < 256) ? embed[(size_t)input_idx[b]*256 + k] : weighted[b*512 + (k-256)];
            continue;
        }
        i -= N3;
        if (i < N4) { int k = i >> 5; int b = i & 31; g_hT[i] = prev_state[b*H_ + k]; continue; }
        i -= N4;
        if (i < N5) { out[OFF_W + i] = 0.f; continue; }
        i -= N5;
        g_rs[i] = 0;
    }
}

// ---- K0b ----
__global__ void k_counts(const int* __restrict__ eidx, const int* __restrict__ input_idx) {
    int gid = blockIdx.x*blockDim.x + threadIdx.x;
    if (gid < M_) {
        int idx = eidx[gid];
        atomicAdd(&g_counts[idx], 1);
        int b = gid >> 11;
        if (idx == input_idx[b]) atomicAdd(&g_rs[b], 1);
    }
}

// ---- K1: GRU gemms ----
__global__ void k_gru_gemm(const float* __restrict__ w_ih, const float* __restrict__ w_hh) {
    const int tid = threadIdx.x;
    const int b = tid & 31;
    const int j = blockIdx.x*8 + (tid >> 5);
    if (blockIdx.y == 0) {
        const float4* wr = (const float4*)(w_ih + (size_t)j*XD_);
        float acc = 0.f;
        #pragma unroll 8
        for (int k4 = 0; k4 < XD_/4; ++k4) {
            float4 wv = wr[k4];
            int k = k4*4;
            acc += wv.x*g_xT[(k+0)*32+b] + wv.y*g_xT[(k+1)*32+b]
                 + wv.z*g_xT[(k+2)*32+b] + wv.w*g_xT[(k+3)*32+b];
        }
        g_gx[j*32+b] = acc;
    } else {
        const float4* wr = (const float4*)(w_hh + (size_t)j*H_);
        float acc = 0.f;
        #pragma unroll 8
        for (int k4 = 0; k4 < H_/4; ++k4) {
            float4 wv = wr[k4];
            int k = k4*4;
            acc += wv.x*g_hT[(k+0)*32+b] + wv.y*g_hT[(k+1)*32+b]
                 + wv.z*g_hT[(k+2)*32+b] + wv.w*g_hT[(k+3)*32+b];
        }
        g_gh[j*32+b] = acc;
    }
}

// ---- K2: gates ----
__global__ void k_gates(const float* __restrict__ b_ih, const float* __restrict__ b_hh,
                        const float* __restrict__ prev_state, float* __restrict__ out)
{
    const int b = blockIdx.x, h = threadIdx.x;
    float xr = g_gx[h*32+b]        + b_ih[h];
    float xz = g_gx[(256+h)*32+b]  + b_ih[256+h];
    float xn = g_gx[(512+h)*32+b]  + b_ih[512+h];
    float hr = g_gh[h*32+b]        + b_hh[h];
    float hz = g_gh[(256+h)*32+b]  + b_hh[256+h];
    float hn = g_gh[(512+h)*32+b]  + b_hh[512+h];
    float r = sigm(xr + hr);
    float z = sigm(xz + hz);
    float n = tanhf(xn + r*hn);
    float st = (1.f - z)*n + z*prev_state[b*H_+h];
    g_state[b*H_+h] = st;
    out[OFF_STATE + b*H_ + h] = st;
}

// ---- K3: score_g ----
__global__ __launch_bounds__(256) void k_score_g(const float* __restrict__ Wo_w,
                                                 const float* __restrict__ Wo_b)
{
    __shared__ float st_s[H_*32];
    const int tid = threadIdx.x;
    for (int i = tid; i < H_*32; i += 256) {
        int k = i >> 5, b = i & 31;
        st_s[i] = g_state[b*H_ + k];
    }
    __syncthreads();
    const int lane = tid & 31;
    const int v0 = blockIdx.x*32 + (tid >> 5)*4;
    if (v0 >= V_) return;
    const float4* w0 = (const float4*)(Wo_w + (size_t)(v0+0)*H_);
    const float4* w1 = (const float4*)(Wo_w + (size_t)(v0+1)*H_);
    const float4* w2 = (const float4*)(Wo_w + (size_t)(v0+2)*H_);
    const float4* w3 = (const float4*)(Wo_w + (size_t)(v0+3)*H_);
    float a0=0.f, a1=0.f, a2=0.f, a3=0.f;
    #pragma unroll 4
    for (int k4 = 0; k4 < H_/4; ++k4) {
        float s0 = st_s[(k4*4+0)*32 + lane];
        float s1 = st_s[(k4*4+1)*32 + lane];
        float s2 = st_s[(k4*4+2)*32 + lane];
        float s3 = st_s[(k4*4+3)*32 + lane];
        float4 q;
        q = w0[k4]; a0 += q.x*s0 + q.y*s1 + q.z*s2 + q.w*s3;
        q = w1[k4]; a1 += q.x*s0 + q.y*s1 + q.z*s2 + q.w*s3;
        q = w2[k4]; a2 += q.x*s0 + q.y*s1 + q.z*s2 + q.w*s3;
        q = w3[k4]; a3 += q.x*s0 + q.y*s1 + q.z*s2 + q.w*s3;
    }
    float4 r;
    r.x = a0 + Wo_b[v0+0];
    r.y = a1 + Wo_b[v0+1];
    r.z = a2 + Wo_b[v0+2];
    r.w = a3 + Wo_b[v0+3];
    *(float4*)(g_score_g + (size_t)lane*V_ + v0) = r;
}

// ---- K4: HMMA bf16-split fused score_c ----
// CTA: 64 tokens x N=256, K=512 in 32 chunks of 16. 8 warps = 2(m) x 4(n), warp tile 32x64.
// 3-term split: Ah*Bh + Ah*Bl + Al*Bh. Epilogue fused: tanh -> dot(state) -> tanh -> mask.
#define PITCH 24   // bf16 units per smem row (48B): conflict-free for frag pattern
__global__ __launch_bounds__(256) void k_score_c(const float* __restrict__ enc,
                                                 const int* __restrict__ eidx,
                                                 const float* __restrict__ wcb)
{
    __shared__ __align__(16) __nv_bfloat16 sAh[64*PITCH], sAl[64*PITCH];
    __shared__ __align__(16) __nv_bfloat16 sBh[256*PITCH], sBl[256*PITCH];
    __shared__ float s_state[256], s_bias[256], s_p[64];

    const int tid = threadIdx.x;
    const int lane = tid & 31;
    const int wid = tid >> 5;
    const int wm = wid >> 2;          // 0..1
    const int wn = wid & 3;           // 0..3
    const int r  = lane >> 2;         // 0..7
    const int q2 = (lane & 3) * 2;    // 0,2,4,6

    const int m0 = blockIdx.x * 64;
    const int b  = m0 >> 11;

    s_state[tid] = g_state[b*H_ + tid];
    s_bias[tid]  = wcb[tid];
    if (tid < 64) s_p[tid] = 0.f;

    float acc[2][8][4];
    #pragma unroll
    for (int mt = 0; mt < 2; ++mt)
        #pragma unroll
        for (int nt = 0; nt < 8; ++nt)
            #pragma unroll
            for (int e = 0; e < 4; ++e) acc[mt][nt][e] = 0.f;

    const int arow = tid >> 2, aseg = tid & 3;       // A loader: 64 rows x 4 segs of 4 floats
    const float* aG = enc + (size_t)(m0 + arow)*KD_ + aseg*4;

    for (int kc = 0; kc < 32; ++kc) {
        // ---- load A chunk (64x16 fp32 -> hi/lo bf16) ----
        {
            float4 f = *(const float4*)(aG + kc*16);
            __nv_bfloat16 hx = __float2bfloat16(f.x), hy = __float2bfloat16(f.y);
            __nv_bfloat16 hz = __float2bfloat16(f.z), hw = __float2bfloat16(f.w);
            __nv_bfloat162 hp0 = __halves2bfloat162(hx, hy);
            __nv_bfloat162 hp1 = __halves2bfloat162(hz, hw);
            __nv_bfloat162 lp0 = __floats2bfloat162_rn(f.x - __bfloat162float(hx),
                                                       f.y - __bfloat162float(hy));
            __nv_bfloat162 lp1 = __floats2bfloat162_rn(f.z - __bfloat162float(hz),
                                                       f.w - __bfloat162float(hw));
            *(uint2*)((char*)sAh + arow*48 + aseg*8) =
                make_uint2(*(unsigned*)&hp0, *(unsigned*)&hp1);
            *(uint2*)((char*)sAl + arow*48 + aseg*8) =
                make_uint2(*(unsigned*)&lp0, *(unsigned*)&lp1);
        }
        // ---- load B chunk (256x16 bf16 hi/lo, pre-split, L2-resident) ----
        #pragma unroll
        for (int j = 0; j < 2; ++j) {
            int i = tid + j*256;          // 0..511
            int row = i >> 1, seg = i & 1;
            size_t goff = (size_t)row*KD_ + kc*16 + seg*8;
            *(uint4*)((char*)sBh + row*48 + seg*16) = *(const uint4*)(g_WcH + goff);
            *(uint4*)((char*)sBl + row*48 + seg*16) = *(const uint4*)(g_WcL + goff);
        }
        __syncthreads();

        // ---- fragments ----
        unsigned ah[2][4], al[2][4], bh[8][2], bl[8][2];
        #pragma unroll
        for (int mt = 0; mt < 2; ++mt) {
            int base = wm*32 + mt*16;
            ah[mt][0] = *(unsigned*)((char*)sAh + (base+r  )*48 + q2*2);
            ah[mt][1] = *(unsigned*)((char*)sAh + (base+r+8)*48 + q2*2);
            ah[mt][2] = *(unsigned*)((char*)sAh + (base+r  )*48 + (q2+8)*2);
            ah[mt][3] = *(unsigned*)((char*)sAh + (base+r+8)*48 + (q2+8)*2);
            al[mt][0] = *(unsigned*)((char*)sAl + (base+r  )*48 + q2*2);
            al[mt][1] = *(unsigned*)((char*)sAl + (base+r+8)*48 + q2*2);
            al[mt][2] = *(unsigned*)((char*)sAl + (base+r  )*48 + (q2+8)*2);
            al[mt][3] = *(unsigned*)((char*)sAl + (base+r+8)*48 + (q2+8)*2);
        }
        #pragma unroll
        for (int nt = 0; nt < 8; ++nt) {
            int nb = wn*64 + nt*8 + r;
            bh[nt][0] = *(unsigned*)((char*)sBh + nb*48 + q2*2);
            bh[nt][1] = *(unsigned*)((char*)sBh + nb*48 + (q2+8)*2);
            bl[nt][0] = *(unsigned*)((char*)sBl + nb*48 + q2*2);
            bl[nt][1] = *(unsigned*)((char*)sBl + nb*48 + (q2+8)*2);
        }
        #pragma unroll
        for (int mt = 0; mt < 2; ++mt)
            #pragma unroll
            for (int nt = 0; nt < 8; ++nt) {
                hmma16816(acc[mt][nt], ah[mt], bh[nt]);
                hmma16816(acc[mt][nt], ah[mt], bl[nt]);
                hmma16816(acc[mt][nt], al[mt], bh[nt]);
            }
        __syncthreads();
    }

    // ---- fused epilogue ----
    #pragma unroll
    for (int mt = 0; mt < 2; ++mt) {
        float p0 = 0.f, p1 = 0.f;
        #pragma unroll
        for (int nt = 0; nt < 8; ++nt) {
            int n0 = wn*64 + nt*8 + q2;
            float b0 = s_bias[n0],  st0 = s_state[n0];
            float b1 = s_bias[n0+1], st1 = s_state[n0+1];
            p0 += tanhf(acc[mt][nt][0] + b0)*st0 + tanhf(acc[mt][nt][1] + b1)*st1;
            p1 += tanhf(acc[mt][nt][2] + b0)*st0 + tanhf(acc[mt][nt][3] + b1)*st1;
        }
        p0 += __shfl_xor_sync(0xffffffffu, p0, 1);
        p0 += __shfl_xor_sync(0xffffffffu, p0, 2);
        p1 += __shfl_xor_sync(0xffffffffu, p1, 1);
        p1 += __shfl_xor_sync(0xffffffffu, p1, 2);
        if ((lane & 3) == 0) {
            atomicAdd(&s_p[wm*32 + mt*16 + r],     p0);
            atomicAdd(&s_p[wm*32 + mt*16 + r + 8], p1);
        }
    }
    __syncthreads();
    if (tid < 64) {
        int m = m0 + tid;
        float v = tanhf(s_p[tid]);
        if (eidx[m] == 0) v -= 1000.f;
        g_score_c[m] = v;
    }
}

// ---- K5a: chunked softmax pass 1 ----
__global__ __launch_bounds__(256) void k_smax1(float* __restrict__ out) {
    __shared__ float buf[4096];
    __shared__ float red[8];
    const int b = blockIdx.y, c = blockIdx.x, tid = threadIdx.x;
    const int i0 = c * 4096;

    float mx = -1e30f;
    for (int t = tid; t < 4096; t += 256) {
        int i = i0 + t;
        float v = -1e30f;
        if (i < V_) v = g_score_g[(size_t)b*V_ + i];
        else if (i < TOT_) v = g_score_c[b*S_ + (i - V_)];
        buf[t] = v;
        mx = fmaxf(mx, v);
    }
    #pragma unroll
    for (int o = 16; o; o >>= 1) mx = fmaxf(mx, __shfl_xor_sync(0xffffffffu, mx, o));
    if ((tid & 31) == 0) red[tid >> 5] = mx;
    __syncthreads();
    if (tid < 8) {
        float v = red[tid];
        #pragma unroll
        for (int o = 4; o; o >>= 1) v = fmaxf(v, __shfl_xor_sync(0xffu, v, o));
        red[tid] = v;
    }
    __syncthreads();
    const float ml = red[0];
    __syncthreads();

    float sum = 0.f;
    for (int t = tid; t < 4096; t += 256) {
        int i = i0 + t;
        if (i < TOT_) {
            float e = expf(buf[t] - ml);
            sum += e;
            if (i < V_) out[(size_t)b*VEXT_ + i] = e;
            else        g_prob_c[b*S_ + (i - V_)] = e;
        }
    }
    #pragma unroll
    for (int o = 16; o; o >>= 1) sum += __shfl_xor_sync(0xffffffffu, sum, o);
    if ((tid & 31) == 0) red[tid >> 5] = sum;
    __syncthreads();
    if (tid == 0) {
        float s = 0.f;
        #pragma unroll
        for (int w = 0; w < 8; ++w) s += red[w];
        g_pm[b*NCH_ + c] = ml;
        g_ps[b*NCH_ + c] = s;
    }
}

// ---- K5b: combine ----
__global__ void k_smax2(float* __restrict__ out) {
    int b = threadIdx.x;
    if (b >= B_) return;
    float m = -1e30f;
    for (int c = 0; c < NCH_; ++c) m = fmaxf(m, g_pm[b*NCH_ + c]);
    float sum = 0.f;
    for (int c = 0; c < NCH_; ++c) sum += g_ps[b*NCH_ + c] * expf(g_pm[b*NCH_ + c] - m);
    float inv = 1.f / sum;
    for (int c = 0; c < NCH_; ++c) g_scale[b*NCH_ + c] = expf(g_pm[b*NCH_ + c] - m) * inv;
    for (int j = 0; j < OOV_; ++j) out[(size_t)b*VEXT_ + V_ + j] = 1e-4f;
}

// ---- K5c: rescale ----
__global__ __launch_bounds__(256) void k_smax3(float* __restrict__ out) {
    const int b = blockIdx.y, c = blockIdx.x, tid = threadIdx.x;
    const int i0 = c * 4096;
    const float s = g_scale[b*NCH_ + c];
    for (int t = tid; t < 4096; t += 256) {
        int i = i0 + t;
        if (i < V_) out[(size_t)b*VEXT_ + i] *= s;
        else if (i < TOT_) g_prob_c[b*S_ + (i - V_)] *= s;
    }
}

// ---- K6: rowsums ----
__global__ void k_rowsums(const int* __restrict__ eidx) {
    int gid = blockIdx.x*blockDim.x + threadIdx.x;
    if (gid < M_) {
        int b = gid >> 11;
        atomicAdd(&g_rowsums[(size_t)b*VEXT_ + eidx[gid]], g_prob_c[gid]);
    }
}

// ---- K7: final scatter + sparse weighted ----
__global__ void k_final(const int* __restrict__ eidx, const int* __restrict__ input_idx,
                        const float* __restrict__ enc, float* __restrict__ out)
{
    int gid = blockIdx.x*blockDim.x + threadIdx.x;
    if (gid >= M_) return;
    int b = gid >> 11;
    int idx = eidx[gid];
    float pc = g_prob_c[gid];
    float attn = pc;
    if (g_counts[idx] > 1) attn = pc * g_rowsums[(size_t)b*VEXT_ + idx];
    atomicAdd(&out[(size_t)b*VEXT_ + idx], attn);

    if (idx == input_idx[b]) {
        int rs = g_rs[b];
        float f = (rs > 1) ? (1.f / (float)rs) : 1.f;
        float a2 = pc * f;
        const float* er = enc + (size_t)gid*KD_;
        for (int d = 0; d < KD_; ++d)
            atomicAdd(&out[OFF_W + b*512 + d], a2 * er[d]);
    }
}

extern "C" void kernel_launch(void* const* d_in, const int* in_sizes, int n_in,
                              void* d_out, int out_size)
{
    const int*   input_idx = (const int*)  d_in[0];
    const float* encoded   = (const float*)d_in[1];
    const int*   eidx      = (const int*)  d_in[2];
    const float* prev_st   = (const float*)d_in[3];
    const float* weighted  = (const float*)d_in[4];
    const float* embed     = (const float*)d_in[6];
    const float* w_ih      = (const float*)d_in[7];
    const float* w_hh      = (const float*)d_in[8];
    const float* b_ih      = (const float*)d_in[9];
    const float* b_hh      = (const float*)d_in[10];
    const float* Wo_w      = (const float*)d_in[11];
    const float* Wo_b      = (const float*)d_in[12];
    const float* Wc_w      = (const float*)d_in[13];
    const float* Wc_b      = (const float*)d_in[14];
    float* out = (float*)d_out;

    k_prep<<<4096, 256>>>(input_idx, embed, weighted, prev_st, Wc_w, out);
    k_counts<<<M_/256, 256>>>(eidx, input_idx);
    k_gru_gemm<<<dim3(96, 2), 256>>>(w_ih, w_hh);
    k_gates<<<B_, H_>>>(b_ih, b_hh, prev_st, out);
    k_score_g<<<(V_ + 31)/32, 256>>>(Wo_w, Wo_b);
    k_score_c<<<M_/64, 256>>>(encoded, eidx, Wc_b);
    k_smax1<<<dim3(NCH_, B_), 256>>>(out);
    k_smax2<<<1, 32>>>(out);
    k_smax3<<<dim3(NCH_, B_), 256>>>(out);
    k_rowsums<<<M_/256, 256>>>(eidx);
    k_final<<<M_/256, 256>>>(eidx, input_idx, encoded, out);
}

// round 5
// speedup vs baseline: 1.7761x; 1.1276x over previous
#include <cuda_runtime.h>
#include <cuda_bf16.h>
#include <math.h>

#define B_    32
#define S_    2048
#define H_    256
#define V_    50000
#define OOV_  12
#define VEXT_ 50012
#define M_    (B_*S_)
#define KD_   512
#define XD_   768
#define TOT_  (V_ + S_)
#define NCH_  13

#define OFF_STATE 1600384
#define OFF_W     1608576

// ---------------- scratch ----------------
__device__ __align__(16) float g_xT[XD_*B_];
__device__ __align__(16) float g_hT[H_*B_];
__device__ __align__(16) float g_gx[768*B_];
__device__ __align__(16) float g_gh[768*B_];
__device__ __align__(16) float g_state[B_*H_];
__device__ __align__(16) float g_score_g[B_*V_];
__device__ __align__(16) float g_score_c[M_];
__device__ __align__(16) float g_prob_c[M_];
__device__            int   g_counts[VEXT_];
__device__            int   g_rs[B_];
__device__ __align__(16) float g_rowsums[B_*VEXT_];
__device__ __align__(16) __nv_bfloat16 g_WcH[H_*KD_];
__device__ __align__(16) __nv_bfloat16 g_WcL[H_*KD_];
__device__ float g_pm[B_*NCH_];
__device__ float g_ps[B_*NCH_];
__device__ float g_gm[B_];
__device__ float g_ginv[B_];

__device__ __forceinline__ float sigm(float x) { return 1.f / (1.f + expf(-x)); }

__device__ __forceinline__ void hmma16816(float* c, const unsigned* a, const unsigned* b) {
    asm volatile(
        "mma.sync.aligned.m16n8k16.row.col.f32.bf16.bf16.f32 "
        "{%0,%1,%2,%3}, {%4,%5,%6,%7}, {%8,%9}, {%0,%1,%2,%3};"
        : "+f"(c[0]), "+f"(c[1]), "+f"(c[2]), "+f"(c[3])
        : "r"(a[0]), "r"(a[1]), "r"(a[2]), "r"(a[3]), "r"(b[0]), "r"(b[1]));
}
__device__ __forceinline__ unsigned smem_u32(const void* p) {
    unsigned a;
    asm("{ .reg .u64 t; cvta.to.shared.u64 t, %1; cvt.u32.u64 %0, t; }" : "=r"(a) : "l"(p));
    return a;
}
__device__ __forceinline__ void cp16(unsigned dst, const void* src) {
    asm volatile("cp.async.cg.shared.global [%0], [%1], 16;"
                 :: "r"(dst), "l"(__cvta_generic_to_global(src)) : "memory");
}
#define CP_COMMIT() asm volatile("cp.async.commit_group;" ::: "memory")
#define CP_WAIT(n)  asm volatile("cp.async.wait_group %0;" :: "n"(n) : "memory")

// ---- K0: zero scratch + Wc split + gathers + counts ----
__global__ void k_prep(const int* __restrict__ input_idx, const float* __restrict__ embed,
                       const float* __restrict__ weighted, const float* __restrict__ prev_state,
                       const float* __restrict__ Wc_w, const int* __restrict__ eidx,
                       float* __restrict__ out)
{
    const int N0 = VEXT_;
    const int N1 = B_*VEXT_;
    const int N2 = H_*KD_;
    const int N3 = XD_*B_;
    const int N4 = H_*B_;
    const int N5 = B_*512;
    const int N6 = B_;
    const int total = N0+N1+N2+N3+N4+N5+N6+M_;
    for (int gid = blockIdx.x*blockDim.x + threadIdx.x; gid < total; gid += gridDim.x*blockDim.x) {
        int i = gid;
        if (i < N0) { g_counts[i] = 0; continue; }
        i -= N0;
        if (i < N1) { g_rowsums[i] = 0.f; continue; }
        i -= N1;
        if (i < N2) {
            float x = Wc_w[i];
            __nv_bfloat16 h = __float2bfloat16(x);
            g_WcH[i] = h;
            g_WcL[i] = __float2bfloat16(x - __bfloat162float(h));
            continue;
        }
        i -= N2;
        if (i < N3) {
            int k = i >> 5; int b = i & 31;
            g_xT[i] = (k < 256) ? embed[(size_t)input_idx[b]*256 + k] : weighted[b*512 + (k-256)];
            continue;
        }
        i -= N3;
        if (i < N4) { int k = i >> 5; int b = i & 31; g_hT[i] = prev_state[b*H_ + k]; continue; }
        i -= N4;
        if (i < N5) { out[OFF_W + i] = 0.f; continue; }
        i -= N5;
        if (i < N6) { g_rs[i] = 0; continue; }
    }
    // counts pass (after zeroing in a separate grid pass would race; do with separate kernel ordering)
}

// ---- K0b: histogram + per-row match count (needs zeros from k_prep) ----
__global__ void k_counts(const int* __restrict__ eidx, const int* __restrict__ input_idx) {
    int gid = blockIdx.x*blockDim.x + threadIdx.x;
    if (gid < M_) {
        int idx = eidx[gid];
        atomicAdd(&g_counts[idx], 1);
        int b = gid >> 11;
        if (idx == input_idx[b]) atomicAdd(&g_rs[b], 1);
    }
}

// ---- K1: GRU gemms ----
__global__ void k_gru_gemm(const float* __restrict__ w_ih, const float* __restrict__ w_hh) {
    const int tid = threadIdx.x;
    const int b = tid & 31;
    const int j = blockIdx.x*8 + (tid >> 5);
    if (blockIdx.y == 0) {
        const float4* wr = (const float4*)(w_ih + (size_t)j*XD_);
        float acc = 0.f;
        #pragma unroll 8
        for (int k4 = 0; k4 < XD_/4; ++k4) {
            float4 wv = wr[k4];
            int k = k4*4;
            acc += wv.x*g_xT[(k+0)*32+b] + wv.y*g_xT[(k+1)*32+b]
                 + wv.z*g_xT[(k+2)*32+b] + wv.w*g_xT[(k+3)*32+b];
        }
        g_gx[j*32+b] = acc;
    } else {
        const float4* wr = (const float4*)(w_hh + (size_t)j*H_);
        float acc = 0.f;
        #pragma unroll 8
        for (int k4 = 0; k4 < H_/4; ++k4) {
            float4 wv = wr[k4];
            int k = k4*4;
            acc += wv.x*g_hT[(k+0)*32+b] + wv.y*g_hT[(k+1)*32+b]
                 + wv.z*g_hT[(k+2)*32+b] + wv.w*g_hT[(k+3)*32+b];
        }
        g_gh[j*32+b] = acc;
    }
}

// ---- K2: gates ----
__global__ void k_gates(const float* __restrict__ b_ih, const float* __restrict__ b_hh,
                        const float* __restrict__ prev_state, float* __restrict__ out)
{
    const int b = blockIdx.x, h = threadIdx.x;
    float xr = g_gx[h*32+b]        + b_ih[h];
    float xz = g_gx[(256+h)*32+b]  + b_ih[256+h];
    float xn = g_gx[(512+h)*32+b]  + b_ih[512+h];
    float hr = g_gh[h*32+b]        + b_hh[h];
    float hz = g_gh[(256+h)*32+b]  + b_hh[256+h];
    float hn = g_gh[(512+h)*32+b]  + b_hh[512+h];
    float r = sigm(xr + hr);
    float z = sigm(xz + hz);
    float n = tanhf(xn + r*hn);
    float st = (1.f - z)*n + z*prev_state[b*H_+h];
    g_state[b*H_+h] = st;
    out[OFF_STATE + b*H_ + h] = st;
}

// ---- K3: score_g ----
__global__ __launch_bounds__(256) void k_score_g(const float* __restrict__ Wo_w,
                                                 const float* __restrict__ Wo_b)
{
    __shared__ float st_s[H_*32];
    const int tid = threadIdx.x;
    for (int i = tid; i < H_*32; i += 256) {
        int k = i >> 5, b = i & 31;
        st_s[i] = g_state[b*H_ + k];
    }
    __syncthreads();
    const int lane = tid & 31;
    const int v0 = blockIdx.x*32 + (tid >> 5)*4;
    if (v0 >= V_) return;
    const float4* w0 = (const float4*)(Wo_w + (size_t)(v0+0)*H_);
    const float4* w1 = (const float4*)(Wo_w + (size_t)(v0+1)*H_);
    const float4* w2 = (const float4*)(Wo_w + (size_t)(v0+2)*H_);
    const float4* w3 = (const float4*)(Wo_w + (size_t)(v0+3)*H_);
    float a0=0.f, a1=0.f, a2=0.f, a3=0.f;
    #pragma unroll 4
    for (int k4 = 0; k4 < H_/4; ++k4) {
        float s0 = st_s[(k4*4+0)*32 + lane];
        float s1 = st_s[(k4*4+1)*32 + lane];
        float s2 = st_s[(k4*4+2)*32 + lane];
        float s3 = st_s[(k4*4+3)*32 + lane];
        float4 q;
        q = w0[k4]; a0 += q.x*s0 + q.y*s1 + q.z*s2 + q.w*s3;
        q = w1[k4]; a1 += q.x*s0 + q.y*s1 + q.z*s2 + q.w*s3;
        q = w2[k4]; a2 += q.x*s0 + q.y*s1 + q.z*s2 + q.w*s3;
        q = w3[k4]; a3 += q.x*s0 + q.y*s1 + q.z*s2 + q.w*s3;
    }
    float4 r;
    r.x = a0 + Wo_b[v0+0];
    r.y = a1 + Wo_b[v0+1];
    r.z = a2 + Wo_b[v0+2];
    r.w = a3 + Wo_b[v0+3];
    *(float4*)(g_score_g + (size_t)lane*V_ + v0) = r;
}

// ---- K4: pipelined HMMA bf16-split fused score_c ----
// CTA: 128 tokens x N=256, K=512 in 16 chunks of 32, cp.async double-buffered.
// 8 warps = 4(m) x 2(n), warp tile 32x128. 3-term split Ah*Bh + Ah*Bl + Al*Bh.
#define OA_  0                 // A fp32: 2 bufs x 128 rows x 144B = 36864
#define OBH_ 36864             // B hi:   2 bufs x 256 rows x 80B  = 40960
#define OBL_ 77824             // B lo:   2 bufs x 256 rows x 80B  = 40960
#define OST_ 118784
#define OBI_ 119808
#define OP_  120832
#define SC_SMEM 121344

__global__ __launch_bounds__(256, 1) void k_score_c(const float* __restrict__ enc,
                                                    const int* __restrict__ eidx,
                                                    const float* __restrict__ wcb)
{
    extern __shared__ __align__(16) char sm[];
    const unsigned sbase = smem_u32(sm);
    const int tid = threadIdx.x;
    const int lane = tid & 31;
    const int wid = tid >> 5;
    const int wm = wid >> 1;          // 0..3
    const int wn = wid & 1;           // 0..1
    const int r  = lane >> 2;         // 0..7
    const int q2 = (lane & 3) * 2;    // 0,2,4,6
    const int m0 = blockIdx.x * 128;
    const int b  = m0 >> 11;

    float* s_state = (float*)(sm + OST_);
    float* s_bias  = (float*)(sm + OBI_);
    float* s_p     = (float*)(sm + OP_);
    s_state[tid] = g_state[b*H_ + tid];
    s_bias[tid]  = wcb[tid];
    if (tid < 128) s_p[tid] = 0.f;

    float acc[2][16][4];
    #pragma unroll
    for (int mt = 0; mt < 2; ++mt)
        #pragma unroll
        for (int nt = 0; nt < 16; ++nt)
            #pragma unroll
            for (int e = 0; e < 4; ++e) acc[mt][nt][e] = 0.f;

    // cp.async issue for chunk kc into buffer bf
    auto issue = [&](int kc, int bf) {
        #pragma unroll
        for (int j = 0; j < 4; ++j) {                 // A: 1024 x 16B
            int i = tid + j*256;
            int row = i >> 3, seg = i & 7;
            cp16(sbase + OA_ + bf*18432 + row*144 + seg*16,
                 enc + (size_t)(m0 + row)*KD_ + kc*32 + seg*4);
        }
        #pragma unroll
        for (int j = 0; j < 4; ++j) {                 // B hi/lo: 1024 x 16B each
            int i = tid + j*256;
            int row = i >> 2, seg = i & 3;
            cp16(sbase + OBH_ + bf*20480 + row*80 + seg*16,
                 g_WcH + (size_t)row*KD_ + kc*32 + seg*8);
            cp16(sbase + OBL_ + bf*20480 + row*80 + seg*16,
                 g_WcL + (size_t)row*KD_ + kc*32 + seg*8);
        }
        CP_COMMIT();
    };

    issue(0, 0);

    for (int kc = 0; kc < 16; ++kc) {
        const int buf = kc & 1;
        if (kc < 15) { issue(kc + 1, buf ^ 1); CP_WAIT(1); }
        else         { CP_WAIT(0); }
        __syncthreads();

        const char* aB  = sm + OA_  + buf*18432;
        const char* bhB = sm + OBH_ + buf*20480;
        const char* blB = sm + OBL_ + buf*20480;

        #pragma unroll
        for (int kg = 0; kg < 2; ++kg) {
            unsigned ah[2][4], al[2][4];
            #pragma unroll
            for (int mt = 0; mt < 2; ++mt) {
                int rowb = wm*32 + mt*16;
                #pragma unroll
                for (int e = 0; e < 4; ++e) {
                    int row = rowb + r + ((e & 1) ? 8 : 0);
                    int ko  = kg*16 + q2 + ((e >= 2) ? 8 : 0);
                    float2 f = *(const float2*)(aB + row*144 + ko*4);
                    __nv_bfloat16 h0 = __float2bfloat16(f.x);
                    __nv_bfloat16 h1 = __float2bfloat16(f.y);
                    __nv_bfloat162 hp = __halves2bfloat162(h0, h1);
                    __nv_bfloat162 lp = __floats2bfloat162_rn(f.x - __bfloat162float(h0),
                                                              f.y - __bfloat162float(h1));
                    ah[mt][e] = *(unsigned*)&hp;
                    al[mt][e] = *(unsigned*)&lp;
                }
            }
            #pragma unroll
            for (int nt = 0; nt < 16; ++nt) {
                int nb = wn*128 + nt*8 + r;
                unsigned bh[2], bl[2];
                bh[0] = *(const unsigned*)(bhB + nb*80 + (kg*16 + q2)*2);
                bh[1] = *(const unsigned*)(bhB + nb*80 + (kg*16 + q2)*2 + 16);
                bl[0] = *(const unsigned*)(blB + nb*80 + (kg*16 + q2)*2);
                bl[1] = *(const unsigned*)(blB + nb*80 + (kg*16 + q2)*2 + 16);
                #pragma unroll
                for (int mt = 0; mt < 2; ++mt) {
                    hmma16816(acc[mt][nt], ah[mt], bh);
                    hmma16816(acc[mt][nt], ah[mt], bl);
                    hmma16816(acc[mt][nt], al[mt], bh);
                }
            }
        }
        __syncthreads();
    }

    // fused epilogue: tanh -> dot(state) -> reduce -> tanh + mask
    #pragma unroll
    for (int mt = 0; mt < 2; ++mt) {
        float p0 = 0.f, p1 = 0.f;
        #pragma unroll
        for (int nt = 0; nt < 16; ++nt) {
            int n0 = wn*128 + nt*8 + q2;
            float b0 = s_bias[n0],  st0 = s_state[n0];
            float b1 = s_bias[n0+1], st1 = s_state[n0+1];
            p0 += tanhf(acc[mt][nt][0] + b0)*st0 + tanhf(acc[mt][nt][1] + b1)*st1;
            p1 += tanhf(acc[mt][nt][2] + b0)*st0 + tanhf(acc[mt][nt][3] + b1)*st1;
        }
        p0 += __shfl_xor_sync(0xffffffffu, p0, 1);
        p0 += __shfl_xor_sync(0xffffffffu, p0, 2);
        p1 += __shfl_xor_sync(0xffffffffu, p1, 1);
        p1 += __shfl_xor_sync(0xffffffffu, p1, 2);
        if ((lane & 3) == 0) {
            atomicAdd(&s_p[wm*32 + mt*16 + r],     p0);
            atomicAdd(&s_p[wm*32 + mt*16 + r + 8], p1);
        }
    }
    __syncthreads();
    if (tid < 128) {
        int m = m0 + tid;
        float v = tanhf(s_p[tid]);
        if (eidx[m] == 0) v -= 1000.f;
        g_score_c[m] = v;
    }
}

// ---- K5a: chunk stats only ----
__global__ __launch_bounds__(256) void k_smax1() {
    __shared__ float buf[4096];
    __shared__ float red[8];
    const int b = blockIdx.y, c = blockIdx.x, tid = threadIdx.x;
    const int i0 = c * 4096;

    float mx = -1e30f;
    for (int t = tid; t < 4096; t += 256) {
        int i = i0 + t;
        float v = -1e30f;
        if (i < V_) v = g_score_g[(size_t)b*V_ + i];
        else if (i < TOT_) v = g_score_c[b*S_ + (i - V_)];
        buf[t] = v;
        mx = fmaxf(mx, v);
    }
    #pragma unroll
    for (int o = 16; o; o >>= 1) mx = fmaxf(mx, __shfl_xor_sync(0xffffffffu, mx, o));
    if ((tid & 31) == 0) red[tid >> 5] = mx;
    __syncthreads();
    if (tid < 8) {
        float v = red[tid];
        #pragma unroll
        for (int o = 4; o; o >>= 1) v = fmaxf(v, __shfl_xor_sync(0xffu, v, o));
        red[tid] = v;
    }
    __syncthreads();
    const float ml = red[0];
    __syncthreads();

    float sum = 0.f;
    for (int t = tid; t < 4096; t += 256) {
        int i = i0 + t;
        if (i < TOT_) sum += expf(buf[t] - ml);
    }
    #pragma unroll
    for (int o = 16; o; o >>= 1) sum += __shfl_xor_sync(0xffffffffu, sum, o);
    if ((tid & 31) == 0) red[tid >> 5] = sum;
    __syncthreads();
    if (tid == 0) {
        float s = 0.f;
        #pragma unroll
        for (int w = 0; w < 8; ++w) s += red[w];
        g_pm[b*NCH_ + c] = ml;
        g_ps[b*NCH_ + c] = s;
    }
}

// ---- K5b: combine ----
__global__ void k_smax2(float* __restrict__ out) {
    int b = threadIdx.x;
    if (b >= B_) return;
    float m = -1e30f;
    for (int c = 0; c < NCH_; ++c) m = fmaxf(m, g_pm[b*NCH_ + c]);
    float sum = 0.f;
    for (int c = 0; c < NCH_; ++c) sum += g_ps[b*NCH_ + c] * expf(g_pm[b*NCH_ + c] - m);
    g_gm[b] = m;
    g_ginv[b] = 1.f / sum;
    for (int j = 0; j < OOV_; ++j) out[(size_t)b*VEXT_ + V_ + j] = 1e-4f;
}

// ---- K5c: write prob_g directly ----
__global__ __launch_bounds__(256) void k_smax3(float* __restrict__ out) {
    const int b = blockIdx.y, c = blockIdx.x, tid = threadIdx.x;
    const int i0 = c * 4096;
    const float m = g_gm[b], inv = g_ginv[b];
    for (int t = tid; t < 4096; t += 256) {
        int i = i0 + t;
        if (i < V_) out[(size_t)b*VEXT_ + i] = expf(g_score_g[(size_t)b*V_ + i] - m) * inv;
    }
}

// ---- K6: prob_c + rowsums ----
__global__ void k_rowsums(const int* __restrict__ eidx) {
    int gid = blockIdx.x*blockDim.x + threadIdx.x;
    if (gid < M_) {
        int b = gid >> 11;
        float pc = expf(g_score_c[gid] - g_gm[b]) * g_ginv[b];
        g_prob_c[gid] = pc;
        atomicAdd(&g_rowsums[(size_t)b*VEXT_ + eidx[gid]], pc);
    }
}

// ---- K7: final scatter + sparse weighted ----
__global__ void k_final(const int* __restrict__ eidx, const int* __restrict__ input_idx,
                        const float* __restrict__ enc, float* __restrict__ out)
{
    int gid = blockIdx.x*blockDim.x + threadIdx.x;
    if (gid >= M_) return;
    int b = gid >> 11;
    int idx = eidx[gid];
    float pc = g_prob_c[gid];
    float attn = pc;
    if (g_counts[idx] > 1) attn = pc * g_rowsums[(size_t)b*VEXT_ + idx];
    atomicAdd(&out[(size_t)b*VEXT_ + idx], attn);

    if (idx == input_idx[b]) {
        int rs = g_rs[b];
        float f = (rs > 1) ? (1.f / (float)rs) : 1.f;
        float a2 = pc * f;
        const float* er = enc + (size_t)gid*KD_;
        for (int d = 0; d < KD_; ++d)
            atomicAdd(&out[OFF_W + b*512 + d], a2 * er[d]);
    }
}

extern "C" void kernel_launch(void* const* d_in, const int* in_sizes, int n_in,
                              void* d_out, int out_size)
{
    const int*   input_idx = (const int*)  d_in[0];
    const float* encoded   = (const float*)d_in[1];
    const int*   eidx      = (const int*)  d_in[2];
    const float* prev_st   = (const float*)d_in[3];
    const float* weighted  = (const float*)d_in[4];
    const float* embed     = (const float*)d_in[6];
    const float* w_ih      = (const float*)d_in[7];
    const float* w_hh      = (const float*)d_in[8];
    const float* b_ih      = (const float*)d_in[9];
    const float* b_hh      = (const float*)d_in[10];
    const float* Wo_w      = (const float*)d_in[11];
    const float* Wo_b      = (const float*)d_in[12];
    const float* Wc_w      = (const float*)d_in[13];
    const float* Wc_b      = (const float*)d_in[14];
    float* out = (float*)d_out;

    cudaFuncSetAttribute(k_score_c, cudaFuncAttributeMaxDynamicSharedMemorySize, SC_SMEM);

    k_prep<<<4096, 256>>>(input_idx, embed, weighted, prev_st, Wc_w, eidx, out);
    k_counts<<<M_/256, 256>>>(eidx, input_idx);
    k_gru_gemm<<<dim3(96, 2), 256>>>(w_ih, w_hh);
    k_gates<<<B_, H_>>>(b_ih, b_hh, prev_st, out);
    k_score_g<<<(V_ + 31)/32, 256>>>(Wo_w, Wo_b);
    k_score_c<<<M_/128, 256, SC_SMEM>>>(encoded, eidx, Wc_b);
    k_smax1<<<dim3(NCH_, B_), 256>>>();
    k_smax2<<<1, 32>>>(out);
    k_smax3<<<dim3(NCH_, B_), 256>>>(out);
    k_rowsums<<<M_/256, 256>>>(eidx);
    k_final<<<M_/256, 256>>>(eidx, input_idx, encoded, out);
}